// round 5
// baseline (speedup 1.0000x reference)
#include <cuda_runtime.h>
#include <cuda_bf16.h>
#include <cstdint>

#define NN 110592
#define CC 128
#define C3 384
#define BB 2
#define GRB 296
#define GEMM_SMEM ((128 * 136 + 2 * 128 * 36) * 4)

typedef unsigned long long ull;

__device__ __nv_bfloat16 g_qkA[(size_t)BB * 256 * NN]; // gemm1 q,k out (bf16)
__device__ float         g_vA [(size_t)BB * CC * NN];  // gemm1 v out (fp32)
__device__ __nv_bfloat16 g_qkB[(size_t)BB * 256 * NN]; // dwconv q,k out (bf16)
__device__ float         g_vB [(size_t)BB * CC * NN];  // dwconv v out (fp32)
__device__ float g_gram[BB * 8 * 16 * 16];
__device__ float g_ssq [BB * 2 * CC];
__device__ float g_W   [BB * CC * CC];

__device__ __forceinline__ unsigned f2tf(float f) {
    unsigned u; asm("cvt.rna.tf32.f32 %0, %1;" : "=r"(u) : "f"(f)); return u;
}
__device__ __forceinline__ float f2tff(float f) { return __uint_as_float(f2tf(f)); }
__device__ __forceinline__ void mma8(float* d, const unsigned* a, const unsigned* b) {
    asm volatile("mma.sync.aligned.m16n8k8.row.col.f32.tf32.tf32.f32 "
                 "{%0,%1,%2,%3}, {%4,%5,%6,%7}, {%8,%9}, {%0,%1,%2,%3};"
                 : "+f"(d[0]), "+f"(d[1]), "+f"(d[2]), "+f"(d[3])
                 : "r"(a[0]), "r"(a[1]), "r"(a[2]), "r"(a[3]), "r"(b[0]), "r"(b[1]));
}
__device__ __forceinline__ ull pack2(float lo, float hi) {
    ull r; asm("mov.b64 %0, {%1, %2};" : "=l"(r) : "f"(lo), "f"(hi)); return r;
}
__device__ __forceinline__ float2 unpack2(ull v) {
    float2 r; asm("mov.b64 {%0, %1}, %2;" : "=f"(r.x), "=f"(r.y) : "l"(v)); return r;
}
__device__ __forceinline__ ull fma2(ull a, ull b, ull c) {
    ull d; asm("fma.rn.f32x2 %0, %1, %2, %3;" : "=l"(d) : "l"(a), "l"(b), "l"(c)); return d;
}
__device__ __forceinline__ ull add2(ull a, ull b) {
    ull d; asm("add.rn.f32x2 %0, %1, %2;" : "=l"(d) : "l"(a), "l"(b)); return d;
}

__global__ void zero_k() {
    int t = blockIdx.x * 256 + threadIdx.x;
    if (t < BB * 8 * 16 * 16) g_gram[t] = 0.f;
    if (t < BB * 2 * CC)      g_ssq[t]  = 0.f;
}

// ------ TF32 GEMM. MODE 0: qkv split epilogue (mt 0,1 -> bf16 qk; mt 2 -> fp32 v).
//        MODE 1: plain fp32 output.
template <int MODE>
__global__ __launch_bounds__(256, 2) void gemm_k(
    const float* __restrict__ A, long long aBatch, long long aTile, int MT,
    const float* __restrict__ B, long long bBatch,
    __nv_bfloat16* __restrict__ Cbf, float* __restrict__ Cf)
{
    extern __shared__ float sm[];
    float* sB = sm;               // [128][136] tf32
    float* sA = sm + 128 * 136;   // [2][128][36] tf32
    const int tid = threadIdx.x;
    const int bn = blockIdx.x, bb = blockIdx.y;
    const float* Ab = A + (long long)bb * aBatch;
    const float* Bb = B + (long long)bb * bBatch + (long long)bn * 128;
    __nv_bfloat16* Cbf_b = (MODE == 0)
        ? Cbf + (long long)bb * 256 * NN + (long long)bn * 128 : nullptr;
    float* Cf_b = Cf + (long long)bb * (long long)CC * NN + (long long)bn * 128;

    {
        const int r0 = tid >> 5, c4 = tid & 31;
        #pragma unroll
        for (int i = 0; i < 16; i++) {
            int r = i * 8 + r0;
            float4 v = *(const float4*)(Bb + (long long)r * NN + c4 * 4);
            *(float4*)(&sB[r * 136 + c4 * 4]) =
                make_float4(f2tff(v.x), f2tff(v.y), f2tff(v.z), f2tff(v.w));
        }
    }

    const int ar = tid >> 3, ac = tid & 7;
    float4 rg[4];
    auto ldA = [&](int mt, int kt) {
        const float* At = Ab + (long long)mt * aTile + kt * 32;
        #pragma unroll
        for (int j = 0; j < 4; j++)
            rg[j] = *(const float4*)(At + (j * 32 + ar) * 128 + ac * 4);
    };
    auto stA = [&](int bufsel) {
        float* base = sA + bufsel * 128 * 36;
        #pragma unroll
        for (int j = 0; j < 4; j++)
            *(float4*)(base + (j * 32 + ar) * 36 + ac * 4) =
                make_float4(f2tff(rg[j].x), f2tff(rg[j].y), f2tff(rg[j].z), f2tff(rg[j].w));
    };

    ldA(0, 0);
    stA(0);
    __syncthreads();

    const int warp = tid >> 5, lane = tid & 31;
    const int wm = warp >> 2, wn = warp & 3;
    const int lr = lane >> 2, lc = lane & 3;

    int buf = 0;
    float acc[4][4][4];
    const int steps = MT * 4;
    for (int step = 0; step < steps; step++) {
        const int mt = step >> 2, kt = step & 3;
        if (kt == 0) {
            #pragma unroll
            for (int a = 0; a < 4; a++)
                #pragma unroll
                for (int b2 = 0; b2 < 4; b2++)
                    #pragma unroll
                    for (int r = 0; r < 4; r++) acc[a][b2][r] = 0.f;
        }
        const bool hasNext = (step + 1 < steps);
        if (hasNext) ldA((step + 1) >> 2, (step + 1) & 3);

        const float* sAb = sA + buf * 128 * 36;
        #pragma unroll
        for (int ks = 0; ks < 4; ks++) {
            const int k = ks * 8;
            const int kk = kt * 32 + k;
            unsigned af[4][4], bfr[4][2];
            #pragma unroll
            for (int mi = 0; mi < 4; mi++) {
                int m0 = wm * 64 + mi * 16;
                af[mi][0] = __float_as_uint(sAb[(m0 + lr) * 36 + k + lc]);
                af[mi][1] = __float_as_uint(sAb[(m0 + 8 + lr) * 36 + k + lc]);
                af[mi][2] = __float_as_uint(sAb[(m0 + lr) * 36 + k + 4 + lc]);
                af[mi][3] = __float_as_uint(sAb[(m0 + 8 + lr) * 36 + k + 4 + lc]);
            }
            #pragma unroll
            for (int ni = 0; ni < 4; ni++) {
                int n0 = wn * 32 + ni * 8;
                bfr[ni][0] = __float_as_uint(sB[(kk + lc) * 136 + n0 + lr]);
                bfr[ni][1] = __float_as_uint(sB[(kk + 4 + lc) * 136 + n0 + lr]);
            }
            #pragma unroll
            for (int mi = 0; mi < 4; mi++)
                #pragma unroll
                for (int ni = 0; ni < 4; ni++)
                    mma8(acc[mi][ni], af[mi], bfr[ni]);
        }
        if (hasNext) stA(buf ^ 1);
        __syncthreads();
        buf ^= 1;

        if (kt == 3) {
            const bool toBf = (MODE == 0) && (mt < 2);
            #pragma unroll
            for (int mi = 0; mi < 4; mi++) {
                int mloc = wm * 64 + mi * 16;
                #pragma unroll
                for (int ni = 0; ni < 4; ni++) {
                    int n0 = wn * 32 + ni * 8;
                    if (toBf) {
                        long long r0 = (long long)(mt * 128 + mloc + lr) * NN + n0 + lc * 2;
                        long long r1 = (long long)(mt * 128 + mloc + 8 + lr) * NN + n0 + lc * 2;
                        *(__nv_bfloat162*)(Cbf_b + r0) =
                            __float22bfloat162_rn(make_float2(acc[mi][ni][0], acc[mi][ni][1]));
                        *(__nv_bfloat162*)(Cbf_b + r1) =
                            __float22bfloat162_rn(make_float2(acc[mi][ni][2], acc[mi][ni][3]));
                    } else {
                        long long r0 = (long long)(mloc + lr) * NN + n0 + lc * 2;
                        long long r1 = (long long)(mloc + 8 + lr) * NN + n0 + lc * 2;
                        *(float2*)(Cf_b + r0) = make_float2(acc[mi][ni][0], acc[mi][ni][1]);
                        *(float2*)(Cf_b + r1) = make_float2(acc[mi][ni][2], acc[mi][ni][3]);
                    }
                }
            }
        }
    }
}

// ------ depthwise 3x3x3, exact fp32 FFMA2 along d. QK=1: bf16 io + ssq; QK=0: fp32 io.
template <int QK>
__global__ __launch_bounds__(192, 2) void dwconv_k(
    const void* __restrict__ in_, const float* __restrict__ wg,
    void* __restrict__ out_)
{
    __shared__ float sP[4][50 * 60];
    __shared__ float sred[192];
    const int hhalf = blockIdx.x, ch = blockIdx.y, b = blockIdx.z;
    const int NCH = QK ? 256 : CC;
    const int tx = threadIdx.x, ty = threadIdx.y;
    const int tid = ty * 24 + tx;
    const int h0 = hhalf * 24;

    for (int i = tid; i < 4 * 3000; i += 192) ((float*)sP)[i] = 0.f;

    ull wp[27];
    {
        const float* wpt = wg + ch * 27;
        #pragma unroll
        for (int i = 0; i < 27; i++) { float w = wpt[i]; wp[i] = pack2(w, w); }
    }
    __syncthreads();

    auto loadPlane = [&](int slot, int hh) {
        float* sp = sP[slot];
        if constexpr (QK) {
            const __nv_bfloat16* base = (const __nv_bfloat16*)in_
                + (long long)(b * NCH + ch) * 48 * 2304;
            const __nv_bfloat162* pl = (const __nv_bfloat162*)(base + (long long)hh * 2304);
            #pragma unroll
            for (int j = 0; j < 6; j++) {
                int l = j * 192 + tid;
                int wr = l / 24, cp = l % 24;
                float2 f = __bfloat1622float2(pl[l]);
                *(float2*)(&sp[(wr + 1) * 60 + 4 + cp * 2]) = f;
            }
        } else {
            const float* base = (const float*)in_ + (long long)(b * NCH + ch) * 48 * 2304;
            const float* pl = base + (long long)hh * 2304;
            #pragma unroll
            for (int j = 0; j < 3; j++) {
                int l = j * 192 + tid;
                int wr = l / 12, q = l % 12;
                float4 v = *(const float4*)(pl + wr * 48 + q * 4);
                *(float4*)(&sp[(wr + 1) * 60 + 4 + q * 4]) = v;
            }
        }
    };
    auto zeroPlane = [&](int slot) {
        float* sp = sP[slot];
        for (int i = tid; i < 3000; i += 192) sp[i] = 0.f;
    };

    if (h0 - 1 >= 0) loadPlane(h0 & 3, h0 - 1);
    loadPlane((h0 + 1) & 3, h0);

    const int t = tx, w0 = ty * 6;
    const int col0 = 2 * t + 3;
    float lssq = 0.f;

    for (int h = h0; h < h0 + 24; h++) {
        if (h + 1 < 48) loadPlane((h + 2) & 3, h + 1);
        else            zeroPlane((h + 2) & 3);
        __syncthreads();
        const float* Ph[3] = {sP[h & 3], sP[(h + 1) & 3], sP[(h + 2) & 3]};

        ull rp[3][3][3];
        #pragma unroll
        for (int hp = 0; hp < 3; hp++)
            #pragma unroll
            for (int s = 0; s < 2; s++) {
                const float* rr = Ph[hp] + (w0 + s) * 60 + col0;
                float v0 = rr[0], v1 = rr[1], v2 = rr[2], v3 = rr[3];
                rp[hp][s][0] = pack2(v0, v1);
                rp[hp][s][1] = pack2(v1, v2);
                rp[hp][s][2] = pack2(v2, v3);
            }

        #pragma unroll
        for (int k = 0; k < 6; k++) {
            const int ns = (k + 2) % 3;
            #pragma unroll
            for (int hp = 0; hp < 3; hp++) {
                const float* rr = Ph[hp] + (w0 + k + 2) * 60 + col0;
                float v0 = rr[0], v1 = rr[1], v2 = rr[2], v3 = rr[3];
                rp[hp][ns][0] = pack2(v0, v1);
                rp[hp][ns][1] = pack2(v1, v2);
                rp[hp][ns][2] = pack2(v2, v3);
            }
            ull a0 = 0ull, a1 = 0ull, a2 = 0ull;
            #pragma unroll
            for (int q = 0; q < 3; q++) {
                const int sl = (k + q) % 3;
                a0 = fma2(wp[0 * 9 + q * 3 + 0], rp[0][sl][0], a0);
                a0 = fma2(wp[0 * 9 + q * 3 + 1], rp[0][sl][1], a0);
                a0 = fma2(wp[0 * 9 + q * 3 + 2], rp[0][sl][2], a0);
                a1 = fma2(wp[1 * 9 + q * 3 + 0], rp[1][sl][0], a1);
                a1 = fma2(wp[1 * 9 + q * 3 + 1], rp[1][sl][1], a1);
                a1 = fma2(wp[1 * 9 + q * 3 + 2], rp[1][sl][2], a1);
                a2 = fma2(wp[2 * 9 + q * 3 + 0], rp[2][sl][0], a2);
                a2 = fma2(wp[2 * 9 + q * 3 + 1], rp[2][sl][1], a2);
                a2 = fma2(wp[2 * 9 + q * 3 + 2], rp[2][sl][2], a2);
            }
            float2 o = unpack2(add2(add2(a0, a1), a2));
            const long long off = (long long)(b * NCH + ch) * 48 * 2304
                                + (long long)h * 2304 + (w0 + k) * 48 + 2 * t;
            if constexpr (QK) {
                __nv_bfloat162 bh = __float22bfloat162_rn(o);
                float2 orr = __bfloat1622float2(bh);
                lssq += orr.x * orr.x + orr.y * orr.y;
                *(__nv_bfloat162*)((__nv_bfloat16*)out_ + off) = bh;
            } else {
                *(float2*)((float*)out_ + off) = o;
            }
        }
    }

    if constexpr (QK) {
        sred[tid] = lssq;
        __syncthreads();
        if (tid < 32) {
            float v = sred[tid] + sred[tid + 32] + sred[tid + 64]
                    + sred[tid + 96] + sred[tid + 128] + sred[tid + 160];
            #pragma unroll
            for (int off = 16; off > 0; off >>= 1)
                v += __shfl_down_sync(0xffffffffu, v, off);
            if (tid == 0) atomicAdd(&g_ssq[b * 256 + ch], v);
        }
    }
}

// ------ Gram (bf16 inputs): G[b,h,i,j] = sum_n q[i,n]*k[j,n] --------------------
__global__ __launch_bounds__(256) void gram_k(const __nv_bfloat16* __restrict__ qk) {
    __shared__ float sq[32 * 257];
    const int tid = threadIdx.x;
    const int b = blockIdx.y;
    const int warp = tid >> 5, lane = tid & 31;
    const int lr4 = lane >> 3, lq = lane & 7;
    const __nv_bfloat16* qkb = qk + (long long)b * 256 * NN;

    uint2 rg[8];
    auto ldC = [&](int c) {
        long long n0 = (long long)c * 32;
        #pragma unroll
        for (int j = 0; j < 8; j++) {
            int row = warp * 32 + j * 4 + lr4;
            rg[j] = *(const uint2*)(qkb + (long long)row * NN + n0 + lq * 4);
        }
    };
    auto stC = [&]() {
        #pragma unroll
        for (int j = 0; j < 8; j++) {
            int row = warp * 32 + j * 4 + lr4;
            float2 lo = __bfloat1622float2(*(const __nv_bfloat162*)&rg[j].x);
            float2 hi = __bfloat1622float2(*(const __nv_bfloat162*)&rg[j].y);
            sq[(lq * 4 + 0) * 257 + row] = lo.x;
            sq[(lq * 4 + 1) * 257 + row] = lo.y;
            sq[(lq * 4 + 2) * 257 + row] = hi.x;
            sq[(lq * 4 + 3) * 257 + row] = hi.y;
        }
    };

    const int h = warp;
    const int it = lane >> 3, jt = (lane >> 1) & 3, nh = lane & 1;
    const int qb = h * 16 + it * 4, kb = 128 + h * 16 + jt * 4;
    float acc[4][4];
    #pragma unroll
    for (int a = 0; a < 4; a++)
        #pragma unroll
        for (int c = 0; c < 4; c++) acc[a][c] = 0.f;

    int c = blockIdx.x;
    ldC(c);
    while (1) {
        stC();
        __syncthreads();
        int cn = c + GRB;
        bool more = cn < NN / 32;
        if (more) ldC(cn);
        #pragma unroll 4
        for (int s = 0; s < 16; s++) {
            const float* rowp = sq + (2 * s + nh) * 257;
            float qv[4], kv[4];
            #pragma unroll
            for (int ii = 0; ii < 4; ii++) qv[ii] = rowp[qb + ii];
            #pragma unroll
            for (int jj = 0; jj < 4; jj++) kv[jj] = rowp[kb + jj];
            #pragma unroll
            for (int ii = 0; ii < 4; ii++)
                #pragma unroll
                for (int jj = 0; jj < 4; jj++)
                    acc[ii][jj] += qv[ii] * kv[jj];
        }
        __syncthreads();
        if (!more) break;
        c = cn;
    }
    #pragma unroll
    for (int ii = 0; ii < 4; ii++)
        #pragma unroll
        for (int jj = 0; jj < 4; jj++)
            acc[ii][jj] += __shfl_xor_sync(0xffffffffu, acc[ii][jj], 1);
    if (nh == 0) {
        #pragma unroll
        for (int ii = 0; ii < 4; ii++)
            #pragma unroll
            for (int jj = 0; jj < 4; jj++)
                atomicAdd(&g_gram[((b * 8 + h) * 16 + it * 4 + ii) * 16 + jt * 4 + jj],
                          acc[ii][jj]);
    }
}

// ------ softmax + W_b = proj_w @ blockdiag(attn_b) ------------------------------
__global__ __launch_bounds__(256) void fold_k(
    const float* __restrict__ proj_w, const float* __restrict__ temp)
{
    __shared__ float sat[8][16][17];
    const int b = blockIdx.x, tid = threadIdx.x;
    if (tid < 128) {
        const int h = tid >> 4, i = tid & 15;
        float nq = fmaxf(sqrtf(g_ssq[b * 256 + h * 16 + i]), 1e-12f);
        float tv = temp[h];
        float row[16];
        float mx = -1e30f;
        #pragma unroll
        for (int j = 0; j < 16; j++) {
            float nk = fmaxf(sqrtf(g_ssq[b * 256 + 128 + h * 16 + j]), 1e-12f);
            float v = g_gram[((b * 8 + h) * 16 + i) * 16 + j] / (nq * nk) * tv;
            row[j] = v;
            mx = fmaxf(mx, v);
        }
        float s = 0.f;
        #pragma unroll
        for (int j = 0; j < 16; j++) { row[j] = expf(row[j] - mx); s += row[j]; }
        const float inv = 1.f / s;
        #pragma unroll
        for (int j = 0; j < 16; j++) sat[h][i][j] = row[j] * inv;
    }
    __syncthreads();
    for (int idx = tid; idx < 16384; idx += 256) {
        const int o = idx >> 7, col = idx & 127;
        const int h = col >> 4, j = col & 15;
        float s = 0.f;
        #pragma unroll
        for (int i = 0; i < 16; i++)
            s += proj_w[o * 128 + h * 16 + i] * sat[h][i][j];
        g_W[b * 16384 + idx] = s;
    }
}

extern "C" void kernel_launch(void* const* d_in, const int* in_sizes, int n_in,
                              void* d_out, int out_size) {
    const float* x      = (const float*)d_in[0];
    const float* qkv_w  = (const float*)d_in[1];
    const float* dw_w   = (const float*)d_in[2];
    const float* proj_w = (const float*)d_in[3];
    const float* temp   = (const float*)d_in[4];
    float* out = (float*)d_out;

    void *p_qkA = nullptr, *p_vA = nullptr, *p_qkB = nullptr, *p_vB = nullptr, *p_W = nullptr;
    cudaGetSymbolAddress(&p_qkA, g_qkA);
    cudaGetSymbolAddress(&p_vA,  g_vA);
    cudaGetSymbolAddress(&p_qkB, g_qkB);
    cudaGetSymbolAddress(&p_vB,  g_vB);
    cudaGetSymbolAddress(&p_W,   g_W);

    cudaFuncSetAttribute(gemm_k<0>, cudaFuncAttributeMaxDynamicSharedMemorySize, GEMM_SMEM);
    cudaFuncSetAttribute(gemm_k<1>, cudaFuncAttributeMaxDynamicSharedMemorySize, GEMM_SMEM);

    zero_k<<<16, 256>>>();

    // qkv = qkv_w @ x : mt 0,1 -> bf16 qk buffer; mt 2 -> fp32 v buffer
    gemm_k<0><<<dim3(NN / 128, BB), 256, GEMM_SMEM>>>(
        qkv_w, 0LL, 128LL * CC, 3,
        x, (long long)CC * NN,
        (__nv_bfloat16*)p_qkA, (float*)p_vA);

    dwconv_k<1><<<dim3(2, 256, BB), dim3(24, 8)>>>(p_qkA, dw_w, p_qkB);
    dwconv_k<0><<<dim3(2, CC, BB), dim3(24, 8)>>>(p_vA, dw_w + 256 * 27, p_vB);

    gram_k<<<dim3(GRB, BB), 256>>>((const __nv_bfloat16*)p_qkB);

    fold_k<<<BB, 256>>>(proj_w, temp);

    // out = W_b @ v
    gemm_k<1><<<dim3(NN / 128, BB), 256, GEMM_SMEM>>>(
        (const float*)p_W, (long long)CC * CC, 0LL, 1,
        (const float*)p_vB, (long long)CC * NN,
        nullptr, out);
}

// round 6
// speedup vs baseline: 1.1243x; 1.1243x over previous
#include <cuda_runtime.h>
#include <cuda_bf16.h>
#include <cstdint>

#define NN 110592
#define CC 128
#define C3 384
#define BB 2
#define GRB 296
#define GEMM_SMEM ((128 * 136 + 2 * 128 * 36) * 4)

__device__ __nv_bfloat16 g_qkA[(size_t)BB * 256 * NN]; // gemm1 q,k out (bf16)
__device__ float         g_vA [(size_t)BB * CC * NN];  // gemm1 v out (fp32)
__device__ __nv_bfloat16 g_qkB[(size_t)BB * 256 * NN]; // dwconv q,k out (bf16)
__device__ float         g_vB [(size_t)BB * CC * NN];  // dwconv v out (fp32)
__device__ float g_gram[BB * 8 * 16 * 16];
__device__ float g_ssq [BB * 2 * CC];
__device__ float g_W   [BB * CC * CC];

__device__ __forceinline__ unsigned f2tf(float f) {
    unsigned u; asm("cvt.rna.tf32.f32 %0, %1;" : "=r"(u) : "f"(f)); return u;
}
__device__ __forceinline__ float f2tff(float f) { return __uint_as_float(f2tf(f)); }
__device__ __forceinline__ void mma8(float* d, const unsigned* a, const unsigned* b) {
    asm volatile("mma.sync.aligned.m16n8k8.row.col.f32.tf32.tf32.f32 "
                 "{%0,%1,%2,%3}, {%4,%5,%6,%7}, {%8,%9}, {%0,%1,%2,%3};"
                 : "+f"(d[0]), "+f"(d[1]), "+f"(d[2]), "+f"(d[3])
                 : "r"(a[0]), "r"(a[1]), "r"(a[2]), "r"(a[3]), "r"(b[0]), "r"(b[1]));
}

__global__ void zero_k() {
    int t = blockIdx.x * 256 + threadIdx.x;
    if (t < BB * 8 * 16 * 16) g_gram[t] = 0.f;
    if (t < BB * 2 * CC)      g_ssq[t]  = 0.f;
}

// ------ TF32 GEMM. MODE 0: qkv split epilogue (mt 0,1 -> bf16 qk; mt 2 -> fp32 v).
//        MODE 1: plain fp32 output.
template <int MODE>
__global__ __launch_bounds__(256, 2) void gemm_k(
    const float* __restrict__ A, long long aBatch, long long aTile, int MT,
    const float* __restrict__ B, long long bBatch,
    __nv_bfloat16* __restrict__ Cbf, float* __restrict__ Cf)
{
    extern __shared__ float sm[];
    float* sB = sm;               // [128][136] tf32
    float* sA = sm + 128 * 136;   // [2][128][36] tf32
    const int tid = threadIdx.x;
    const int bn = blockIdx.x, bb = blockIdx.y;
    const float* Ab = A + (long long)bb * aBatch;
    const float* Bb = B + (long long)bb * bBatch + (long long)bn * 128;
    __nv_bfloat16* Cbf_b = (MODE == 0)
        ? Cbf + (long long)bb * 256 * NN + (long long)bn * 128 : nullptr;
    float* Cf_b = Cf + (long long)bb * (long long)CC * NN + (long long)bn * 128;

    {
        const int r0 = tid >> 5, c4 = tid & 31;
        #pragma unroll
        for (int i = 0; i < 16; i++) {
            int r = i * 8 + r0;
            float4 v = *(const float4*)(Bb + (long long)r * NN + c4 * 4);
            *(float4*)(&sB[r * 136 + c4 * 4]) =
                make_float4(f2tff(v.x), f2tff(v.y), f2tff(v.z), f2tff(v.w));
        }
    }

    const int ar = tid >> 3, ac = tid & 7;
    float4 rg[4];
    auto ldA = [&](int mt, int kt) {
        const float* At = Ab + (long long)mt * aTile + kt * 32;
        #pragma unroll
        for (int j = 0; j < 4; j++)
            rg[j] = *(const float4*)(At + (j * 32 + ar) * 128 + ac * 4);
    };
    auto stA = [&](int bufsel) {
        float* base = sA + bufsel * 128 * 36;
        #pragma unroll
        for (int j = 0; j < 4; j++)
            *(float4*)(base + (j * 32 + ar) * 36 + ac * 4) =
                make_float4(f2tff(rg[j].x), f2tff(rg[j].y), f2tff(rg[j].z), f2tff(rg[j].w));
    };

    ldA(0, 0);
    stA(0);
    __syncthreads();

    const int warp = tid >> 5, lane = tid & 31;
    const int wm = warp >> 2, wn = warp & 3;
    const int lr = lane >> 2, lc = lane & 3;

    int buf = 0;
    float acc[4][4][4];
    const int steps = MT * 4;
    for (int step = 0; step < steps; step++) {
        const int mt = step >> 2, kt = step & 3;
        if (kt == 0) {
            #pragma unroll
            for (int a = 0; a < 4; a++)
                #pragma unroll
                for (int b2 = 0; b2 < 4; b2++)
                    #pragma unroll
                    for (int r = 0; r < 4; r++) acc[a][b2][r] = 0.f;
        }
        const bool hasNext = (step + 1 < steps);
        if (hasNext) ldA((step + 1) >> 2, (step + 1) & 3);

        const float* sAb = sA + buf * 128 * 36;
        #pragma unroll
        for (int ks = 0; ks < 4; ks++) {
            const int k = ks * 8;
            const int kk = kt * 32 + k;
            unsigned af[4][4], bfr[4][2];
            #pragma unroll
            for (int mi = 0; mi < 4; mi++) {
                int m0 = wm * 64 + mi * 16;
                af[mi][0] = __float_as_uint(sAb[(m0 + lr) * 36 + k + lc]);
                af[mi][1] = __float_as_uint(sAb[(m0 + 8 + lr) * 36 + k + lc]);
                af[mi][2] = __float_as_uint(sAb[(m0 + lr) * 36 + k + 4 + lc]);
                af[mi][3] = __float_as_uint(sAb[(m0 + 8 + lr) * 36 + k + 4 + lc]);
            }
            #pragma unroll
            for (int ni = 0; ni < 4; ni++) {
                int n0 = wn * 32 + ni * 8;
                bfr[ni][0] = __float_as_uint(sB[(kk + lc) * 136 + n0 + lr]);
                bfr[ni][1] = __float_as_uint(sB[(kk + 4 + lc) * 136 + n0 + lr]);
            }
            #pragma unroll
            for (int mi = 0; mi < 4; mi++)
                #pragma unroll
                for (int ni = 0; ni < 4; ni++)
                    mma8(acc[mi][ni], af[mi], bfr[ni]);
        }
        if (hasNext) stA(buf ^ 1);
        __syncthreads();
        buf ^= 1;

        if (kt == 3) {
            const bool toBf = (MODE == 0) && (mt < 2);
            #pragma unroll
            for (int mi = 0; mi < 4; mi++) {
                int mloc = wm * 64 + mi * 16;
                #pragma unroll
                for (int ni = 0; ni < 4; ni++) {
                    int n0 = wn * 32 + ni * 8;
                    if (toBf) {
                        long long r0 = (long long)(mt * 128 + mloc + lr) * NN + n0 + lc * 2;
                        long long r1 = (long long)(mt * 128 + mloc + 8 + lr) * NN + n0 + lc * 2;
                        *(__nv_bfloat162*)(Cbf_b + r0) =
                            __float22bfloat162_rn(make_float2(acc[mi][ni][0], acc[mi][ni][1]));
                        *(__nv_bfloat162*)(Cbf_b + r1) =
                            __float22bfloat162_rn(make_float2(acc[mi][ni][2], acc[mi][ni][3]));
                    } else {
                        long long r0 = (long long)(mloc + lr) * NN + n0 + lc * 2;
                        long long r1 = (long long)(mloc + 8 + lr) * NN + n0 + lc * 2;
                        *(float2*)(Cf_b + r0) = make_float2(acc[mi][ni][0], acc[mi][ni][1]);
                        *(float2*)(Cf_b + r1) = make_float2(acc[mi][ni][2], acc[mi][ni][3]);
                    }
                }
            }
        }
    }
}

// ------ depthwise 3x3x3 scalar sliding-window, unified launch --------------------
// grid (2 h-halves, 384 ch, BB). ch<256: bf16 io + ssq; ch>=256: fp32 io.
// threads (48 d, 4 w-groups of 12). 4-plane smem ring.
__global__ __launch_bounds__(192, 3) void dwconv_k(
    const __nv_bfloat16* __restrict__ qk_in, const float* __restrict__ v_in,
    const float* __restrict__ wg,
    __nv_bfloat16* __restrict__ qk_out, float* __restrict__ v_out)
{
    __shared__ float sP[4][50 * 60];
    __shared__ float sred[192];
    const int hhalf = blockIdx.x, ch = blockIdx.y, b = blockIdx.z;
    const int tx = threadIdx.x, ty = threadIdx.y;
    const int tid = ty * 48 + tx;
    const int h0 = hhalf * 24;
    const bool isQK = (ch < 256);

    for (int i = tid; i < 4 * 3000; i += 192) ((float*)sP)[i] = 0.f;

    float wv[27];
    {
        const float* wp = wg + ch * 27;
        #pragma unroll
        for (int i = 0; i < 27; i++) wv[i] = wp[i];
    }
    __syncthreads();

    const __nv_bfloat16* qbase = qk_in + (long long)(b * 256 + ch) * 48 * 2304;
    const float* vbase = v_in + (long long)(b * CC + (ch - 256)) * 48 * 2304;

    auto loadPlane = [&](int slot, int hh) {
        float* sp = sP[slot];
        if (isQK) {
            const __nv_bfloat162* pl = (const __nv_bfloat162*)(qbase + (long long)hh * 2304);
            #pragma unroll
            for (int j = 0; j < 6; j++) {
                int l = j * 192 + tid;            // pair index 0..1151
                int wr = l / 24, cp = l % 24;
                float2 f = __bfloat1622float2(pl[l]);
                *(float2*)(&sp[(wr + 1) * 60 + 4 + cp * 2]) = f;
            }
        } else {
            const float* pl = vbase + (long long)hh * 2304;
            #pragma unroll
            for (int j = 0; j < 3; j++) {
                int l = j * 192 + tid;
                int wr = l / 12, q = l % 12;
                float4 v = *(const float4*)(pl + wr * 48 + q * 4);
                *(float4*)(&sp[(wr + 1) * 60 + 4 + q * 4]) = v;
            }
        }
    };
    auto zeroPlane = [&](int slot) {
        float* sp = sP[slot];
        for (int i = tid; i < 3000; i += 192) sp[i] = 0.f;
    };

    if (h0 - 1 >= 0) loadPlane(h0 & 3, h0 - 1);
    loadPlane((h0 + 1) & 3, h0);

    const int d = tx, w0 = ty * 12;
    float lssq = 0.f;
    __nv_bfloat16* qob0 = qk_out + (long long)(b * 256 + ch) * 48 * 2304;
    float* vob0 = v_out + (long long)(b * CC + (ch - 256)) * 48 * 2304;

    for (int h = h0; h < h0 + 24; h++) {
        if (h + 1 < 48) loadPlane((h + 2) & 3, h + 1);
        else            zeroPlane((h + 2) & 3);
        __syncthreads();
        const float* P0 = sP[h & 3];
        const float* P1 = sP[(h + 1) & 3];
        const float* P2 = sP[(h + 2) & 3];

        float r[3][3][3];  // [w-slot][hp][dp]
        #pragma unroll
        for (int dp = 0; dp < 3; dp++) {
            r[0][0][dp] = P0[w0 * 60 + d + 3 + dp];
            r[0][1][dp] = P1[w0 * 60 + d + 3 + dp];
            r[0][2][dp] = P2[w0 * 60 + d + 3 + dp];
            r[1][0][dp] = P0[(w0 + 1) * 60 + d + 3 + dp];
            r[1][1][dp] = P1[(w0 + 1) * 60 + d + 3 + dp];
            r[1][2][dp] = P2[(w0 + 1) * 60 + d + 3 + dp];
        }
        const long long rowoff = (long long)h * 2304;
        #pragma unroll
        for (int k = 0; k < 12; k++) {
            const int ns = (k + 2) % 3;
            #pragma unroll
            for (int dp = 0; dp < 3; dp++) {
                r[ns][0][dp] = P0[(w0 + k + 2) * 60 + d + 3 + dp];
                r[ns][1][dp] = P1[(w0 + k + 2) * 60 + d + 3 + dp];
                r[ns][2][dp] = P2[(w0 + k + 2) * 60 + d + 3 + dp];
            }
            float o = 0.f;
            #pragma unroll
            for (int hp = 0; hp < 3; hp++)
                #pragma unroll
                for (int q = 0; q < 3; q++) {
                    const int sl = (k + q) % 3;
                    #pragma unroll
                    for (int dp = 0; dp < 3; dp++)
                        o += wv[hp * 9 + q * 3 + dp] * r[sl][hp][dp];
                }
            const long long off = rowoff + (w0 + k) * 48 + d;
            if (isQK) {
                __nv_bfloat16 bh = __float2bfloat16_rn(o);
                float orr = __bfloat162float(bh);
                lssq += orr * orr;
                qob0[off] = bh;
            } else {
                vob0[off] = o;
            }
        }
    }

    if (isQK) {
        sred[tid] = lssq;
        __syncthreads();
        if (tid < 32) {
            float v = sred[tid] + sred[tid + 32] + sred[tid + 64]
                    + sred[tid + 96] + sred[tid + 128] + sred[tid + 160];
            #pragma unroll
            for (int off = 16; off > 0; off >>= 1)
                v += __shfl_down_sync(0xffffffffu, v, off);
            if (tid == 0) atomicAdd(&g_ssq[b * 256 + ch], v);
        }
    }
}

// ------ Gram (bf16 inputs): G[b,h,i,j] = sum_n q[i,n]*k[j,n] --------------------
__global__ __launch_bounds__(256) void gram_k(const __nv_bfloat16* __restrict__ qk) {
    __shared__ float sq[32 * 257];
    const int tid = threadIdx.x;
    const int b = blockIdx.y;
    const int warp = tid >> 5, lane = tid & 31;
    const int lr4 = lane >> 3, lq = lane & 7;
    const __nv_bfloat16* qkb = qk + (long long)b * 256 * NN;

    uint2 rg[8];
    auto ldC = [&](int c) {
        long long n0 = (long long)c * 32;
        #pragma unroll
        for (int j = 0; j < 8; j++) {
            int row = warp * 32 + j * 4 + lr4;
            rg[j] = *(const uint2*)(qkb + (long long)row * NN + n0 + lq * 4);
        }
    };
    auto stC = [&]() {
        #pragma unroll
        for (int j = 0; j < 8; j++) {
            int row = warp * 32 + j * 4 + lr4;
            float2 lo = __bfloat1622float2(*(const __nv_bfloat162*)&rg[j].x);
            float2 hi = __bfloat1622float2(*(const __nv_bfloat162*)&rg[j].y);
            sq[(lq * 4 + 0) * 257 + row] = lo.x;
            sq[(lq * 4 + 1) * 257 + row] = lo.y;
            sq[(lq * 4 + 2) * 257 + row] = hi.x;
            sq[(lq * 4 + 3) * 257 + row] = hi.y;
        }
    };

    const int h = warp;
    const int it = lane >> 3, jt = (lane >> 1) & 3, nh = lane & 1;
    const int qb = h * 16 + it * 4, kb = 128 + h * 16 + jt * 4;
    float acc[4][4];
    #pragma unroll
    for (int a = 0; a < 4; a++)
        #pragma unroll
        for (int c = 0; c < 4; c++) acc[a][c] = 0.f;

    int c = blockIdx.x;
    ldC(c);
    while (1) {
        stC();
        __syncthreads();
        int cn = c + GRB;
        bool more = cn < NN / 32;
        if (more) ldC(cn);
        #pragma unroll 4
        for (int s = 0; s < 16; s++) {
            const float* rowp = sq + (2 * s + nh) * 257;
            float qv[4], kv[4];
            #pragma unroll
            for (int ii = 0; ii < 4; ii++) qv[ii] = rowp[qb + ii];
            #pragma unroll
            for (int jj = 0; jj < 4; jj++) kv[jj] = rowp[kb + jj];
            #pragma unroll
            for (int ii = 0; ii < 4; ii++)
                #pragma unroll
                for (int jj = 0; jj < 4; jj++)
                    acc[ii][jj] += qv[ii] * kv[jj];
        }
        __syncthreads();
        if (!more) break;
        c = cn;
    }
    #pragma unroll
    for (int ii = 0; ii < 4; ii++)
        #pragma unroll
        for (int jj = 0; jj < 4; jj++)
            acc[ii][jj] += __shfl_xor_sync(0xffffffffu, acc[ii][jj], 1);
    if (nh == 0) {
        #pragma unroll
        for (int ii = 0; ii < 4; ii++)
            #pragma unroll
            for (int jj = 0; jj < 4; jj++)
                atomicAdd(&g_gram[((b * 8 + h) * 16 + it * 4 + ii) * 16 + jt * 4 + jj],
                          acc[ii][jj]);
    }
}

// ------ softmax + W_b = proj_w @ blockdiag(attn_b) ------------------------------
__global__ __launch_bounds__(256) void fold_k(
    const float* __restrict__ proj_w, const float* __restrict__ temp)
{
    __shared__ float sat[8][16][17];
    const int b = blockIdx.x, tid = threadIdx.x;
    if (tid < 128) {
        const int h = tid >> 4, i = tid & 15;
        float nq = fmaxf(sqrtf(g_ssq[b * 256 + h * 16 + i]), 1e-12f);
        float tv = temp[h];
        float row[16];
        float mx = -1e30f;
        #pragma unroll
        for (int j = 0; j < 16; j++) {
            float nk = fmaxf(sqrtf(g_ssq[b * 256 + 128 + h * 16 + j]), 1e-12f);
            float v = g_gram[((b * 8 + h) * 16 + i) * 16 + j] / (nq * nk) * tv;
            row[j] = v;
            mx = fmaxf(mx, v);
        }
        float s = 0.f;
        #pragma unroll
        for (int j = 0; j < 16; j++) { row[j] = expf(row[j] - mx); s += row[j]; }
        const float inv = 1.f / s;
        #pragma unroll
        for (int j = 0; j < 16; j++) sat[h][i][j] = row[j] * inv;
    }
    __syncthreads();
    for (int idx = tid; idx < 16384; idx += 256) {
        const int o = idx >> 7, col = idx & 127;
        const int h = col >> 4, j = col & 15;
        float s = 0.f;
        #pragma unroll
        for (int i = 0; i < 16; i++)
            s += proj_w[o * 128 + h * 16 + i] * sat[h][i][j];
        g_W[b * 16384 + idx] = s;
    }
}

extern "C" void kernel_launch(void* const* d_in, const int* in_sizes, int n_in,
                              void* d_out, int out_size) {
    const float* x      = (const float*)d_in[0];
    const float* qkv_w  = (const float*)d_in[1];
    const float* dw_w   = (const float*)d_in[2];
    const float* proj_w = (const float*)d_in[3];
    const float* temp   = (const float*)d_in[4];
    float* out = (float*)d_out;

    void *p_qkA = nullptr, *p_vA = nullptr, *p_qkB = nullptr, *p_vB = nullptr, *p_W = nullptr;
    cudaGetSymbolAddress(&p_qkA, g_qkA);
    cudaGetSymbolAddress(&p_vA,  g_vA);
    cudaGetSymbolAddress(&p_qkB, g_qkB);
    cudaGetSymbolAddress(&p_vB,  g_vB);
    cudaGetSymbolAddress(&p_W,   g_W);

    cudaFuncSetAttribute(gemm_k<0>, cudaFuncAttributeMaxDynamicSharedMemorySize, GEMM_SMEM);
    cudaFuncSetAttribute(gemm_k<1>, cudaFuncAttributeMaxDynamicSharedMemorySize, GEMM_SMEM);

    zero_k<<<16, 256>>>();

    // qkv = qkv_w @ x : mt 0,1 -> bf16 qk buffer; mt 2 -> fp32 v buffer
    gemm_k<0><<<dim3(NN / 128, BB), 256, GEMM_SMEM>>>(
        qkv_w, 0LL, 128LL * CC, 3,
        x, (long long)CC * NN,
        (__nv_bfloat16*)p_qkA, (float*)p_vA);

    dwconv_k<<<dim3(2, C3, BB), dim3(48, 4)>>>(
        (const __nv_bfloat16*)p_qkA, (const float*)p_vA, dw_w,
        (__nv_bfloat16*)p_qkB, (float*)p_vB);

    gram_k<<<dim3(GRB, BB), 256>>>((const __nv_bfloat16*)p_qkB);

    fold_k<<<BB, 256>>>(proj_w, temp);

    // out = W_b @ v
    gemm_k<1><<<dim3(NN / 128, BB), 256, GEMM_SMEM>>>(
        (const float*)p_W, (long long)CC * CC, 0LL, 1,
        (const float*)p_vB, (long long)CC * NN,
        nullptr, out);
}

// round 7
// speedup vs baseline: 1.1865x; 1.0553x over previous
#include <cuda_runtime.h>
#include <cuda_bf16.h>
#include <cstdint>

#define NN 110592
#define CC 128
#define C3 384
#define BB 2
#define GRB 296
#define GEMM_SMEM ((128 * 136 + 2 * 128 * 36) * 4)

__device__ __nv_bfloat16 g_qkA[(size_t)BB * 256 * NN]; // gemm1 q,k out (bf16)
__device__ float         g_vA [(size_t)BB * CC * NN];  // gemm1 v out (fp32)
__device__ __nv_bfloat16 g_qkB[(size_t)BB * 256 * NN]; // dwconv q,k out (bf16)
__device__ float         g_vB [(size_t)BB * CC * NN];  // dwconv v out (fp32)
__device__ float g_gram[BB * 8 * 16 * 16];
__device__ float g_ssq [BB * 2 * CC];
__device__ float g_W   [BB * CC * CC];

__device__ __forceinline__ unsigned f2tf(float f) {
    unsigned u; asm("cvt.rna.tf32.f32 %0, %1;" : "=r"(u) : "f"(f)); return u;
}
__device__ __forceinline__ float f2tff(float f) { return __uint_as_float(f2tf(f)); }
__device__ __forceinline__ void mma8(float* d, const unsigned* a, const unsigned* b) {
    asm volatile("mma.sync.aligned.m16n8k8.row.col.f32.tf32.tf32.f32 "
                 "{%0,%1,%2,%3}, {%4,%5,%6,%7}, {%8,%9}, {%0,%1,%2,%3};"
                 : "+f"(d[0]), "+f"(d[1]), "+f"(d[2]), "+f"(d[3])
                 : "r"(a[0]), "r"(a[1]), "r"(a[2]), "r"(a[3]), "r"(b[0]), "r"(b[1]));
}
__device__ __forceinline__ void mma16816bf(float* d, const unsigned* a, const unsigned* b) {
    asm volatile("mma.sync.aligned.m16n8k16.row.col.f32.bf16.bf16.f32 "
                 "{%0,%1,%2,%3}, {%4,%5,%6,%7}, {%8,%9}, {%0,%1,%2,%3};"
                 : "+f"(d[0]), "+f"(d[1]), "+f"(d[2]), "+f"(d[3])
                 : "r"(a[0]), "r"(a[1]), "r"(a[2]), "r"(a[3]), "r"(b[0]), "r"(b[1]));
}
__device__ __forceinline__ void ldmx4(unsigned* r, unsigned addr) {
    asm volatile("ldmatrix.sync.aligned.m8n8.x4.shared.b16 {%0,%1,%2,%3}, [%4];"
                 : "=r"(r[0]), "=r"(r[1]), "=r"(r[2]), "=r"(r[3]) : "r"(addr));
}

__global__ void zero_k() {
    int t = blockIdx.x * 256 + threadIdx.x;
    if (t < BB * 8 * 16 * 16) g_gram[t] = 0.f;
    if (t < BB * 2 * CC)      g_ssq[t]  = 0.f;
}

// ------ TF32 GEMM. MODE 0: qkv split epilogue (mt 0,1 -> bf16 qk; mt 2 -> fp32 v).
//        MODE 1: plain fp32 output.
template <int MODE>
__global__ __launch_bounds__(256, 2) void gemm_k(
    const float* __restrict__ A, long long aBatch, long long aTile, int MT,
    const float* __restrict__ B, long long bBatch,
    __nv_bfloat16* __restrict__ Cbf, float* __restrict__ Cf)
{
    extern __shared__ float sm[];
    float* sB = sm;               // [128][136] tf32
    float* sA = sm + 128 * 136;   // [2][128][36] tf32
    const int tid = threadIdx.x;
    const int bn = blockIdx.x, bb = blockIdx.y;
    const float* Ab = A + (long long)bb * aBatch;
    const float* Bb = B + (long long)bb * bBatch + (long long)bn * 128;
    __nv_bfloat16* Cbf_b = (MODE == 0)
        ? Cbf + (long long)bb * 256 * NN + (long long)bn * 128 : nullptr;
    float* Cf_b = Cf + (long long)bb * (long long)CC * NN + (long long)bn * 128;

    {
        const int r0 = tid >> 5, c4 = tid & 31;
        #pragma unroll
        for (int i = 0; i < 16; i++) {
            int r = i * 8 + r0;
            float4 v = *(const float4*)(Bb + (long long)r * NN + c4 * 4);
            *(float4*)(&sB[r * 136 + c4 * 4]) =
                make_float4(f2tff(v.x), f2tff(v.y), f2tff(v.z), f2tff(v.w));
        }
    }

    const int ar = tid >> 3, ac = tid & 7;
    float4 rg[4];
    auto ldA = [&](int mt, int kt) {
        const float* At = Ab + (long long)mt * aTile + kt * 32;
        #pragma unroll
        for (int j = 0; j < 4; j++)
            rg[j] = *(const float4*)(At + (j * 32 + ar) * 128 + ac * 4);
    };
    auto stA = [&](int bufsel) {
        float* base = sA + bufsel * 128 * 36;
        #pragma unroll
        for (int j = 0; j < 4; j++)
            *(float4*)(base + (j * 32 + ar) * 36 + ac * 4) =
                make_float4(f2tff(rg[j].x), f2tff(rg[j].y), f2tff(rg[j].z), f2tff(rg[j].w));
    };

    ldA(0, 0);
    stA(0);
    __syncthreads();

    const int warp = tid >> 5, lane = tid & 31;
    const int wm = warp >> 2, wn = warp & 3;
    const int lr = lane >> 2, lc = lane & 3;

    int buf = 0;
    float acc[4][4][4];
    const int steps = MT * 4;
    for (int step = 0; step < steps; step++) {
        const int mt = step >> 2, kt = step & 3;
        if (kt == 0) {
            #pragma unroll
            for (int a = 0; a < 4; a++)
                #pragma unroll
                for (int b2 = 0; b2 < 4; b2++)
                    #pragma unroll
                    for (int r = 0; r < 4; r++) acc[a][b2][r] = 0.f;
        }
        const bool hasNext = (step + 1 < steps);
        if (hasNext) ldA((step + 1) >> 2, (step + 1) & 3);

        const float* sAb = sA + buf * 128 * 36;
        #pragma unroll
        for (int ks = 0; ks < 4; ks++) {
            const int k = ks * 8;
            const int kk = kt * 32 + k;
            unsigned af[4][4], bfr[4][2];
            #pragma unroll
            for (int mi = 0; mi < 4; mi++) {
                int m0 = wm * 64 + mi * 16;
                af[mi][0] = __float_as_uint(sAb[(m0 + lr) * 36 + k + lc]);
                af[mi][1] = __float_as_uint(sAb[(m0 + 8 + lr) * 36 + k + lc]);
                af[mi][2] = __float_as_uint(sAb[(m0 + lr) * 36 + k + 4 + lc]);
                af[mi][3] = __float_as_uint(sAb[(m0 + 8 + lr) * 36 + k + 4 + lc]);
            }
            #pragma unroll
            for (int ni = 0; ni < 4; ni++) {
                int n0 = wn * 32 + ni * 8;
                bfr[ni][0] = __float_as_uint(sB[(kk + lc) * 136 + n0 + lr]);
                bfr[ni][1] = __float_as_uint(sB[(kk + 4 + lc) * 136 + n0 + lr]);
            }
            #pragma unroll
            for (int mi = 0; mi < 4; mi++)
                #pragma unroll
                for (int ni = 0; ni < 4; ni++)
                    mma8(acc[mi][ni], af[mi], bfr[ni]);
        }
        if (hasNext) stA(buf ^ 1);
        __syncthreads();
        buf ^= 1;

        if (kt == 3) {
            const bool toBf = (MODE == 0) && (mt < 2);
            #pragma unroll
            for (int mi = 0; mi < 4; mi++) {
                int mloc = wm * 64 + mi * 16;
                #pragma unroll
                for (int ni = 0; ni < 4; ni++) {
                    int n0 = wn * 32 + ni * 8;
                    if (toBf) {
                        long long r0 = (long long)(mt * 128 + mloc + lr) * NN + n0 + lc * 2;
                        long long r1 = (long long)(mt * 128 + mloc + 8 + lr) * NN + n0 + lc * 2;
                        *(__nv_bfloat162*)(Cbf_b + r0) =
                            __float22bfloat162_rn(make_float2(acc[mi][ni][0], acc[mi][ni][1]));
                        *(__nv_bfloat162*)(Cbf_b + r1) =
                            __float22bfloat162_rn(make_float2(acc[mi][ni][2], acc[mi][ni][3]));
                    } else {
                        long long r0 = (long long)(mloc + lr) * NN + n0 + lc * 2;
                        long long r1 = (long long)(mloc + 8 + lr) * NN + n0 + lc * 2;
                        *(float2*)(Cf_b + r0) = make_float2(acc[mi][ni][0], acc[mi][ni][1]);
                        *(float2*)(Cf_b + r1) = make_float2(acc[mi][ni][2], acc[mi][ni][3]);
                    }
                }
            }
        }
    }
}

// ------ depthwise 3x3x3 scalar sliding-window, unified launch --------------------
__global__ __launch_bounds__(192, 3) void dwconv_k(
    const __nv_bfloat16* __restrict__ qk_in, const float* __restrict__ v_in,
    const float* __restrict__ wg,
    __nv_bfloat16* __restrict__ qk_out, float* __restrict__ v_out)
{
    __shared__ float sP[4][50 * 60];
    __shared__ float sred[192];
    const int hhalf = blockIdx.x, ch = blockIdx.y, b = blockIdx.z;
    const int tx = threadIdx.x, ty = threadIdx.y;
    const int tid = ty * 48 + tx;
    const int h0 = hhalf * 24;
    const bool isQK = (ch < 256);

    for (int i = tid; i < 4 * 3000; i += 192) ((float*)sP)[i] = 0.f;

    float wv[27];
    {
        const float* wp = wg + ch * 27;
        #pragma unroll
        for (int i = 0; i < 27; i++) wv[i] = wp[i];
    }
    __syncthreads();

    const __nv_bfloat16* qbase = qk_in + (long long)(b * 256 + ch) * 48 * 2304;
    const float* vbase = v_in + (long long)(b * CC + (ch - 256)) * 48 * 2304;

    auto loadPlane = [&](int slot, int hh) {
        float* sp = sP[slot];
        if (isQK) {
            const __nv_bfloat162* pl = (const __nv_bfloat162*)(qbase + (long long)hh * 2304);
            #pragma unroll
            for (int j = 0; j < 6; j++) {
                int l = j * 192 + tid;
                int wr = l / 24, cp = l % 24;
                float2 f = __bfloat1622float2(pl[l]);
                *(float2*)(&sp[(wr + 1) * 60 + 4 + cp * 2]) = f;
            }
        } else {
            const float* pl = vbase + (long long)hh * 2304;
            #pragma unroll
            for (int j = 0; j < 3; j++) {
                int l = j * 192 + tid;
                int wr = l / 12, q = l % 12;
                float4 v = *(const float4*)(pl + wr * 48 + q * 4);
                *(float4*)(&sp[(wr + 1) * 60 + 4 + q * 4]) = v;
            }
        }
    };
    auto zeroPlane = [&](int slot) {
        float* sp = sP[slot];
        for (int i = tid; i < 3000; i += 192) sp[i] = 0.f;
    };

    if (h0 - 1 >= 0) loadPlane(h0 & 3, h0 - 1);
    loadPlane((h0 + 1) & 3, h0);

    const int d = tx, w0 = ty * 12;
    float lssq = 0.f;
    __nv_bfloat16* qob0 = qk_out + (long long)(b * 256 + ch) * 48 * 2304;
    float* vob0 = v_out + (long long)(b * CC + (ch - 256)) * 48 * 2304;

    for (int h = h0; h < h0 + 24; h++) {
        if (h + 1 < 48) loadPlane((h + 2) & 3, h + 1);
        else            zeroPlane((h + 2) & 3);
        __syncthreads();
        const float* P0 = sP[h & 3];
        const float* P1 = sP[(h + 1) & 3];
        const float* P2 = sP[(h + 2) & 3];

        float r[3][3][3];
        #pragma unroll
        for (int dp = 0; dp < 3; dp++) {
            r[0][0][dp] = P0[w0 * 60 + d + 3 + dp];
            r[0][1][dp] = P1[w0 * 60 + d + 3 + dp];
            r[0][2][dp] = P2[w0 * 60 + d + 3 + dp];
            r[1][0][dp] = P0[(w0 + 1) * 60 + d + 3 + dp];
            r[1][1][dp] = P1[(w0 + 1) * 60 + d + 3 + dp];
            r[1][2][dp] = P2[(w0 + 1) * 60 + d + 3 + dp];
        }
        const long long rowoff = (long long)h * 2304;
        #pragma unroll
        for (int k = 0; k < 12; k++) {
            const int ns = (k + 2) % 3;
            #pragma unroll
            for (int dp = 0; dp < 3; dp++) {
                r[ns][0][dp] = P0[(w0 + k + 2) * 60 + d + 3 + dp];
                r[ns][1][dp] = P1[(w0 + k + 2) * 60 + d + 3 + dp];
                r[ns][2][dp] = P2[(w0 + k + 2) * 60 + d + 3 + dp];
            }
            float o = 0.f;
            #pragma unroll
            for (int hp = 0; hp < 3; hp++)
                #pragma unroll
                for (int q = 0; q < 3; q++) {
                    const int sl = (k + q) % 3;
                    #pragma unroll
                    for (int dp = 0; dp < 3; dp++)
                        o += wv[hp * 9 + q * 3 + dp] * r[sl][hp][dp];
                }
            const long long off = rowoff + (w0 + k) * 48 + d;
            if (isQK) {
                __nv_bfloat16 bh = __float2bfloat16_rn(o);
                float orr = __bfloat162float(bh);
                lssq += orr * orr;
                qob0[off] = bh;
            } else {
                vob0[off] = o;
            }
        }
    }

    if (isQK) {
        sred[tid] = lssq;
        __syncthreads();
        if (tid < 32) {
            float v = sred[tid] + sred[tid + 32] + sred[tid + 64]
                    + sred[tid + 96] + sred[tid + 128] + sred[tid + 160];
            #pragma unroll
            for (int off = 16; off > 0; off >>= 1)
                v += __shfl_down_sync(0xffffffffu, v, off);
            if (tid == 0) atomicAdd(&g_ssq[b * 256 + ch], v);
        }
    }
}

// ------ Gram via bf16 tensor cores --------------------------------------------
// smem sq[256 rows][40 bf16] (80B stride: conflict-free ldmatrix).
// warp = head h: A = q rows h*16.., B = k rows 128+h*16.. ; 2 k-steps x 2 mma per chunk.
__global__ __launch_bounds__(256) void gram_k(const __nv_bfloat16* __restrict__ qk) {
    __shared__ __nv_bfloat16 sq[256 * 40];
    const int tid = threadIdx.x;
    const int b = blockIdx.y;
    const int warp = tid >> 5, lane = tid & 31;
    const int lr4 = lane >> 3, lq = lane & 7;
    const __nv_bfloat16* qkb = qk + (long long)b * 256 * NN;

    uint2 rg[8];
    auto ldC = [&](int c) {
        long long n0 = (long long)c * 32;
        #pragma unroll
        for (int j = 0; j < 8; j++) {
            int row = warp * 32 + j * 4 + lr4;
            rg[j] = *(const uint2*)(qkb + (long long)row * NN + n0 + lq * 4);
        }
    };
    auto stC = [&]() {
        #pragma unroll
        for (int j = 0; j < 8; j++) {
            int row = warp * 32 + j * 4 + lr4;
            *(uint2*)(&sq[row * 40 + lq * 4]) = rg[j];
        }
    };

    const int h = warp;
    // ldmatrix lane-address bases (bytes, shared space)
    const int aRow = h * 16 + (lane & 7) + ((lane >> 3) & 1) * 8;
    const unsigned aAddr = (unsigned)__cvta_generic_to_shared(&sq[aRow * 40])
                         + ((lane >> 4) & 1) * 16;
    const int bRow = 128 + h * 16 + (lane & 7) + ((lane >> 4) & 1) * 8;
    const unsigned bAddr = (unsigned)__cvta_generic_to_shared(&sq[bRow * 40])
                         + ((lane >> 3) & 1) * 16;

    float acc[2][4];
    #pragma unroll
    for (int jh = 0; jh < 2; jh++)
        #pragma unroll
        for (int r = 0; r < 4; r++) acc[jh][r] = 0.f;

    int c = blockIdx.x;
    ldC(c);
    while (1) {
        stC();
        __syncthreads();
        int cn = c + GRB;
        bool more = cn < NN / 32;
        if (more) ldC(cn);
        #pragma unroll
        for (int ks = 0; ks < 2; ks++) {
            unsigned a[4], bb[4];
            ldmx4(a, aAddr + ks * 32);
            ldmx4(bb, bAddr + ks * 32);
            mma16816bf(acc[0], a, bb + 0);
            mma16816bf(acc[1], a, bb + 2);
        }
        __syncthreads();
        if (!more) break;
        c = cn;
    }

    // C fragment: c0 (row, col), c1 (row, col+1), c2 (row+8, col), c3 (row+8, col+1)
    const int row = lane >> 2, col = (lane & 3) * 2;
    float* G = &g_gram[(b * 8 + h) * 256];
    #pragma unroll
    for (int jh = 0; jh < 2; jh++) {
        const int j0 = jh * 8 + col;
        atomicAdd(&G[row * 16 + j0],           acc[jh][0]);
        atomicAdd(&G[row * 16 + j0 + 1],       acc[jh][1]);
        atomicAdd(&G[(row + 8) * 16 + j0],     acc[jh][2]);
        atomicAdd(&G[(row + 8) * 16 + j0 + 1], acc[jh][3]);
    }
}

// ------ softmax + W_b = proj_w @ blockdiag(attn_b) ------------------------------
__global__ __launch_bounds__(256) void fold_k(
    const float* __restrict__ proj_w, const float* __restrict__ temp)
{
    __shared__ float sat[8][16][17];
    const int b = blockIdx.x, tid = threadIdx.x;
    if (tid < 128) {
        const int h = tid >> 4, i = tid & 15;
        float nq = fmaxf(sqrtf(g_ssq[b * 256 + h * 16 + i]), 1e-12f);
        float tv = temp[h];
        float row[16];
        float mx = -1e30f;
        #pragma unroll
        for (int j = 0; j < 16; j++) {
            float nk = fmaxf(sqrtf(g_ssq[b * 256 + 128 + h * 16 + j]), 1e-12f);
            float v = g_gram[((b * 8 + h) * 16 + i) * 16 + j] / (nq * nk) * tv;
            row[j] = v;
            mx = fmaxf(mx, v);
        }
        float s = 0.f;
        #pragma unroll
        for (int j = 0; j < 16; j++) { row[j] = expf(row[j] - mx); s += row[j]; }
        const float inv = 1.f / s;
        #pragma unroll
        for (int j = 0; j < 16; j++) sat[h][i][j] = row[j] * inv;
    }
    __syncthreads();
    for (int idx = tid; idx < 16384; idx += 256) {
        const int o = idx >> 7, col = idx & 127;
        const int h = col >> 4, j = col & 15;
        float s = 0.f;
        #pragma unroll
        for (int i = 0; i < 16; i++)
            s += proj_w[o * 128 + h * 16 + i] * sat[h][i][j];
        g_W[b * 16384 + idx] = s;
    }
}

extern "C" void kernel_launch(void* const* d_in, const int* in_sizes, int n_in,
                              void* d_out, int out_size) {
    const float* x      = (const float*)d_in[0];
    const float* qkv_w  = (const float*)d_in[1];
    const float* dw_w   = (const float*)d_in[2];
    const float* proj_w = (const float*)d_in[3];
    const float* temp   = (const float*)d_in[4];
    float* out = (float*)d_out;

    void *p_qkA = nullptr, *p_vA = nullptr, *p_qkB = nullptr, *p_vB = nullptr, *p_W = nullptr;
    cudaGetSymbolAddress(&p_qkA, g_qkA);
    cudaGetSymbolAddress(&p_vA,  g_vA);
    cudaGetSymbolAddress(&p_qkB, g_qkB);
    cudaGetSymbolAddress(&p_vB,  g_vB);
    cudaGetSymbolAddress(&p_W,   g_W);

    cudaFuncSetAttribute(gemm_k<0>, cudaFuncAttributeMaxDynamicSharedMemorySize, GEMM_SMEM);
    cudaFuncSetAttribute(gemm_k<1>, cudaFuncAttributeMaxDynamicSharedMemorySize, GEMM_SMEM);

    zero_k<<<16, 256>>>();

    // qkv = qkv_w @ x : mt 0,1 -> bf16 qk buffer; mt 2 -> fp32 v buffer
    gemm_k<0><<<dim3(NN / 128, BB), 256, GEMM_SMEM>>>(
        qkv_w, 0LL, 128LL * CC, 3,
        x, (long long)CC * NN,
        (__nv_bfloat16*)p_qkA, (float*)p_vA);

    dwconv_k<<<dim3(2, C3, BB), dim3(48, 4)>>>(
        (const __nv_bfloat16*)p_qkA, (const float*)p_vA, dw_w,
        (__nv_bfloat16*)p_qkB, (float*)p_vB);

    gram_k<<<dim3(GRB, BB), 256>>>((const __nv_bfloat16*)p_qkB);

    fold_k<<<BB, 256>>>(proj_w, temp);

    // out = W_b @ v
    gemm_k<1><<<dim3(NN / 128, BB), 256, GEMM_SMEM>>>(
        (const float*)p_W, (long long)CC * CC, 0LL, 1,
        (const float*)p_vB, (long long)CC * NN,
        nullptr, out);
}